// round 10
// baseline (speedup 1.0000x reference)
#include <cuda_runtime.h>
#include <cuda_fp16.h>
#include <cstdint>

// ---- SMEM layout (bytes): 7 x 32KB unpadded swizzled fp16 tiles + 3KB small ----
#define OFF_OUTA 0
#define OFF_OUTB 32768
#define OFF_HA   65536
#define OFF_HB   98304
#define OFF_WIM  131072
#define OFF_W1   163840
#define OFF_W2   196608
#define OFF_C0   229376   // float2 (wz,bi)[128] = 1KB ; ALIASED as sOA float[256]
#define OFF_WF   230400   // float[2][128] double-buffered Wf = 1KB
#define OFF_B12  231424   // float2 (b1,b2)[128] = 1KB
#define SMEM_TOTAL 232448

// ---- device scratch ----
__device__ __half g_WiM[(size_t)128 * 16384];  // per-i swizzled 128x128 fp16 image
__device__ float  g_wz[128 * 128];
__device__ __half g_W1h[16384];                // swizzled image
__device__ __half g_W2h[16384];
__device__ float  g_zT[(size_t)128 * 131072];  // [i][b]

// XOR-swizzled byte offset in a 128x128 fp16 tile (row = 256B)
__host__ __device__ __forceinline__ uint32_t tile_off(int r, int c) {
    return (uint32_t)(r * 256 + ((c * 2) ^ ((r & 7) << 4)));
}

// ---- prologue kernels ----
__global__ void prep_weights(const float* __restrict__ Wi, const float* __restrict__ M,
                             const float* __restrict__ W1, const float* __restrict__ W2) {
    int i = blockIdx.x;
    if (i < 128) {
        const float* Wii = Wi + (size_t)i * 16512;   // 128*129
        for (int v = threadIdx.x; v < 16384; v += blockDim.x) {
            int j = v >> 7, k = v & 127;
            float m = (k == i) ? 0.f : M[k * 128 + i];
            g_WiM[(size_t)i * 16384 + (tile_off(j, k) >> 1)] = __float2half(Wii[j * 129 + k] * m);
        }
        for (int j = threadIdx.x; j < 128; j += blockDim.x)
            g_wz[i * 128 + j] = Wii[j * 129 + 128];
    } else if (i == 128) {
        for (int v = threadIdx.x; v < 16384; v += blockDim.x)
            g_W1h[tile_off(v >> 7, v & 127) >> 1] = __float2half(W1[v]);
    } else {
        for (int v = threadIdx.x; v < 16384; v += blockDim.x)
            g_W2h[tile_off(v >> 7, v & 127) >> 1] = __float2half(W2[v]);
    }
}

__global__ void transpose_z(const float* __restrict__ z, int Bn) {
    __shared__ float t[32][33];
    int b0 = blockIdx.x * 32, i0 = blockIdx.y * 32;
    #pragma unroll
    for (int r = threadIdx.y; r < 32; r += 8)
        t[r][threadIdx.x] = z[(size_t)(b0 + r) * 128 + i0 + threadIdx.x];
    __syncthreads();
    #pragma unroll
    for (int r = threadIdx.y; r < 32; r += 8)
        g_zT[(size_t)(i0 + r) * Bn + b0 + threadIdx.x] = t[threadIdx.x][r];
}

// ---- mma helpers ----
__device__ __forceinline__ void ldsm4(uint32_t addr, uint32_t* r) {
    asm volatile("ldmatrix.sync.aligned.m8n8.x4.shared.b16 {%0,%1,%2,%3},[%4];"
        : "=r"(r[0]), "=r"(r[1]), "=r"(r[2]), "=r"(r[3]) : "r"(addr));
}
__device__ __forceinline__ void mma16816(float* c, const uint32_t* a, const uint32_t* b) {
    asm volatile("mma.sync.aligned.m16n8k16.row.col.f32.f16.f16.f32 "
        "{%0,%1,%2,%3},{%4,%5,%6,%7},{%8,%9},{%0,%1,%2,%3};"
        : "+f"(c[0]), "+f"(c[1]), "+f"(c[2]), "+f"(c[3])
        : "r"(a[0]), "r"(a[1]), "r"(a[2]), "r"(a[3]), "r"(b[0]), "r"(b[1]));
}
__device__ __forceinline__ void cpa16(uint32_t s, const void* g) {
    asm volatile("cp.async.cg.shared.global [%0],[%1],16;" :: "r"(s), "l"(g));
}

// ============ unit GEMM + interleaved epilogue chunk of the OTHER unit ============
// Unit = NMT*16-row group starting at rbG (G side) / rbE (E side) of a 128-row tile.
// EPI: 0 none | 1 relu(accE + z*wz + bi)->H | 2 relu(accE + b1)->H | 3 fc_f dot->p
template<int EPI, int NMT>
__device__ __forceinline__ void gemm_u(
    uint32_t aTile, int rbG, uint32_t bBase,
    float (*accG)[8][4], const float (*accE)[8][4],
    char* hTile, int rbE,
    const float2* sC0, const float2* sB12, const float* sWfc,
    const float* zv, float (*p)[2],
    int lane, int ncol)
{
    #pragma unroll
    for (int mt = 0; mt < NMT; mt++)
        #pragma unroll
        for (int nt = 0; nt < 8; nt++)
            #pragma unroll
            for (int c = 0; c < 4; c++) accG[mt][nt][c] = 0.f;

    const int gr0 = lane >> 2, gc0 = 2 * (lane & 3);
    const int rA = rbG + (lane & 15);
    const uint32_t rowA0 = aTile + (uint32_t)(rA * 256);
    const uint32_t xorA = (uint32_t)((rA & 7) << 4);
    const uint32_t cA = (lane & 16) ? 16u : 0u;
    const int rB = ncol + (lane & 7) + ((lane & 16) ? 8 : 0);
    const uint32_t rowW = bBase + (uint32_t)(rB * 256);
    const uint32_t xorB = (uint32_t)((lane & 7) << 4);
    const uint32_t cB = (lane & 8) ? 16u : 0u;
    const uint32_t xrE = (uint32_t)(gr0 << 4);

    #pragma unroll
    for (int ks = 0; ks < 8; ks++) {
        uint32_t offA = ((uint32_t)(ks * 32) + cA) ^ xorA;
        uint32_t offB = ((uint32_t)(ks * 32) + cB) ^ xorB;
        uint32_t a0[4], a1[4], b[16];
        ldsm4(rowA0 + offA, a0);
        if (NMT == 2) ldsm4(rowA0 + 4096 + offA, a1);
        #pragma unroll
        for (int q = 0; q < 4; q++) ldsm4(rowW + (uint32_t)(q * 4096) + offB, b + 4 * q);
        #pragma unroll
        for (int nt = 0; nt < 8; nt++) {
            const uint32_t* bb = b + (nt >> 1) * 4 + (nt & 1) * 2;
            mma16816(accG[0][nt], a0, bb);
            if (NMT == 2) mma16816(accG[1][nt], a1, bb);
        }
        // ---- epilogue chunk nt=ks for the E unit ----
        if (EPI == 1 || EPI == 2) {
            const int nt = ks;
            const int c = ncol + nt * 8 + gc0;
            float x0, x1, za0 = 0.f, za1 = 0.f;
            if (EPI == 1) { float2 t0 = sC0[c], t1 = sC0[c + 1];
                            x0 = t0.y; x1 = t1.y; za0 = t0.x; za1 = t1.x; }
            else          { x0 = sB12[c].x; x1 = sB12[c + 1].x; }
            const uint32_t cb = ((uint32_t)(2 * c)) ^ xrE;
            #pragma unroll
            for (int mt = 0; mt < NMT; mt++) {
                const int r0 = rbE + mt * 16 + gr0, r1 = r0 + 8;
                float v00 = accE[mt][nt][0], v01 = accE[mt][nt][1];
                float v10 = accE[mt][nt][2], v11 = accE[mt][nt][3];
                if (EPI == 1) {
                    const float zlo = zv[mt * 2], zhi = zv[mt * 2 + 1];
                    v00 = fmaf(zlo, za0, v00); v01 = fmaf(zlo, za1, v01);
                    v10 = fmaf(zhi, za0, v10); v11 = fmaf(zhi, za1, v11);
                }
                v00 = fmaxf(v00 + x0, 0.f); v01 = fmaxf(v01 + x1, 0.f);
                v10 = fmaxf(v10 + x0, 0.f); v11 = fmaxf(v11 + x1, 0.f);
                *(__half2*)(hTile + r0 * 256 + cb) = __floats2half2_rn(v00, v01);
                *(__half2*)(hTile + r1 * 256 + cb) = __floats2half2_rn(v10, v11);
            }
        }
        if (EPI == 3) {
            const int nt = ks;
            const int c = ncol + nt * 8 + gc0;
            const float wf0 = sWfc[c], wf1 = sWfc[c + 1];
            const float q0 = sB12[c].y, q1 = sB12[c + 1].y;
            #pragma unroll
            for (int mt = 0; mt < NMT; mt++) {
                p[mt][0] = fmaf(fmaxf(accE[mt][nt][0] + q0, 0.f), wf0,
                           fmaf(fmaxf(accE[mt][nt][1] + q1, 0.f), wf1, p[mt][0]));
                p[mt][1] = fmaf(fmaxf(accE[mt][nt][2] + q0, 0.f), wf0,
                           fmaf(fmaxf(accE[mt][nt][3] + q1, 0.f), wf1, p[mt][1]));
            }
        }
    }
}

// exposed fc_f dot (post-loop tail only)
template<int NMT>
__device__ __forceinline__ void dot_exposed(const float (*accE)[8][4],
    const float* sWfc, const float2* sB12, int ncol, int lane, float (*p)[2]) {
    const int gc0 = 2 * (lane & 3);
    #pragma unroll
    for (int nt = 0; nt < 8; nt++) {
        const int c = ncol + nt * 8 + gc0;
        const float wf0 = sWfc[c], wf1 = sWfc[c + 1];
        const float q0 = sB12[c].y, q1 = sB12[c + 1].y;
        #pragma unroll
        for (int mt = 0; mt < NMT; mt++) {
            p[mt][0] = fmaf(fmaxf(accE[mt][nt][0] + q0, 0.f), wf0,
                       fmaf(fmaxf(accE[mt][nt][1] + q1, 0.f), wf1, p[mt][0]));
            p[mt][1] = fmaf(fmaxf(accE[mt][nt][2] + q0, 0.f), wf0,
                       fmaf(fmaxf(accE[mt][nt][3] + q1, 0.f), wf1, p[mt][1]));
        }
    }
}

// cross-lane reduce of fc_f partials into sO[wn*128 + row]
template<int NMT>
__device__ __forceinline__ void reduce_u(float (*p)[2], float* sO, int wn, int rbE, int lane) {
    const int gr0 = lane >> 2;
    #pragma unroll
    for (int mt = 0; mt < NMT; mt++)
        #pragma unroll
        for (int hh = 0; hh < 2; hh++) {
            float v = p[mt][hh];
            v += __shfl_xor_sync(0xffffffffu, v, 1);
            v += __shfl_xor_sync(0xffffffffu, v, 2);
            if ((lane & 3) == 0)
                sO[wn * 128 + rbE + mt * 16 + hh * 8 + gr0] = v;
        }
}

// ==================== pair kernel: units = two 128-row tiles ====================
__global__ __launch_bounds__(256, 1)
void gen_pair(const float* __restrict__ x,  const float* __restrict__ bi,
              const float* __restrict__ Wf, const float* __restrict__ bf,
              const float* __restrict__ b1, const float* __restrict__ b2,
              float* __restrict__ out, int Bn, int baseRow)
{
    extern __shared__ char sm[];
    const int tid = threadIdx.x, lane = tid & 31, wid = tid >> 5;
    const int wm = wid >> 1, wn = wid & 1;
    const int mrow = wm * 32, ncol = wn * 64;
    const int gr0 = lane >> 2;
    const size_t b0 = (size_t)baseRow + (size_t)blockIdx.x * 256;

    const uint32_t smBase = (uint32_t)__cvta_generic_to_shared(sm);
    const uint32_t aOutA = smBase + OFF_OUTA, aOutB = smBase + OFF_OUTB;
    const uint32_t aHA = smBase + OFF_HA, aHB = smBase + OFF_HB;
    const uint32_t aWiM = smBase + OFF_WIM, aW1 = smBase + OFF_W1, aW2 = smBase + OFF_W2;
    char* hA = sm + OFF_HA; char* hB = sm + OFF_HB;
    char* outA = sm + OFF_OUTA; char* outB = sm + OFF_OUTB;
    float2* sC0  = (float2*)(sm + OFF_C0);
    float*  sOA  = (float*)(sm + OFF_C0);      // alias; sC0 dead after P2
    float*  sOB  = (float*)hB;                 // stash; hB dead from prev step P5 .. this P2
    float*  sWfD = (float*)(sm + OFF_WF);      // [2][128]
    float2* sB12 = (float2*)(sm + OFF_B12);

    // ---- stage x into both tiles ----
    const float4* xg = (const float4*)(x + b0 * 128);
    #pragma unroll
    for (int q = 0; q < 32; q++) {
        int v = (q << 8) + tid;
        float4 f = xg[v];
        int rv = v >> 5, c4 = (v & 31) << 2;
        uint32_t off = tile_off(rv & 127, c4);
        char* base = sm + ((rv >> 7) ? OFF_OUTB : OFF_OUTA);
        *(__half2*)(base + off)     = __floats2half2_rn(f.x, f.y);
        *(__half2*)(base + off + 4) = __floats2half2_rn(f.z, f.w);
    }
    #pragma unroll
    for (int q = 0; q < 8; q++) {
        int v = (q << 8) + tid;
        ((uint4*)(sm + OFF_W1))[v] = ((const uint4*)g_W1h)[v];
        ((uint4*)(sm + OFF_W2))[v] = ((const uint4*)g_W2h)[v];
        cpa16(aWiM + (uint32_t)(v << 4), ((const uint4*)g_WiM) + v);
    }
    asm volatile("cp.async.commit_group;");
    if (tid < 128) sB12[tid] = make_float2(b1[tid], b2[tid]);
    asm volatile("cp.async.wait_group 0;");
    __syncthreads();

    float accA[2][8][4], accB[2][8][4];

    for (int i = 0; i < 128; i++) {
        if (i) { asm volatile("cp.async.wait_group 0;"); __syncthreads(); }  // S0
        if (tid < 128) sWfD[(i & 1) * 128 + tid] = Wf[(i << 7) + tid];
        const float* sWfCur  = sWfD + (i & 1) * 128;
        const float* sWfPrev = sWfD + ((i & 1) ^ 1) * 128;

        // ---- P0: G0a + (i>0: E2b dot of prev step) ----
        float pB[2][2] = {{0.f, 0.f}, {0.f, 0.f}};
        if (i) {
            gemm_u<3, 2>(aOutA, mrow, aWiM, accA, accB, hB, mrow,
                         sC0, sB12, sWfPrev, nullptr, pB, lane, ncol);
            reduce_u<2>(pB, sOB, wn, mrow, lane);
        } else {
            gemm_u<0, 2>(aOutA, mrow, aWiM, accA, accB, hB, mrow,
                         sC0, sB12, sWfCur, nullptr, pB, lane, ncol);
        }
        __syncthreads();                                   // S1: sOB visible; G0a done
        if (i && tid < 128) {
            float o = sOB[tid] + sOB[128 + tid] + bf[i - 1];
            out[(b0 + 128 + tid) * 128 + (i - 1)] = o;
            *(__half*)(outB + tile_off(tid, i - 1)) = __float2half(o);
        }
        if (tid < 128) sC0[tid] = make_float2(g_wz[(i << 7) + tid], bi[(i << 7) + tid]);
        __syncthreads();                                   // S1b: OUT_b col + sC0 visible

        const float* zg = g_zT + (size_t)i * Bn + b0;
        float zvA[4] = { zg[mrow + gr0], zg[mrow + 8 + gr0], zg[mrow + 16 + gr0], zg[mrow + 24 + gr0] };
        float zvB[4] = { zg[128 + mrow + gr0], zg[136 + mrow + gr0], zg[144 + mrow + gr0], zg[152 + mrow + gr0] };

        // ---- P1: G0b + E0a -> hA ----
        gemm_u<1, 2>(aOutB, mrow, aWiM, accB, accA, hA, mrow,
                     sC0, sB12, sWfCur, zvA, (float(*)[2])nullptr, lane, ncol);
        __syncthreads();                                   // S2: WiM reads done; hA ready
        if (i < 127) {
            const uint4* src = (const uint4*)(g_WiM + (size_t)(i + 1) * 16384);
            #pragma unroll
            for (int q = 0; q < 8; q++) {
                int v = (q << 8) + tid;
                cpa16(aWiM + (uint32_t)(v << 4), src + v);
            }
            asm volatile("cp.async.commit_group;");
        }
        // ---- P2: G1a + E0b -> hB ----
        gemm_u<1, 2>(aHA, mrow, aW1, accA, accB, hB, mrow,
                     sC0, sB12, sWfCur, zvB, (float(*)[2])nullptr, lane, ncol);
        __syncthreads();                                   // S3
        // ---- P3: G1b + E1a -> hA ----
        gemm_u<2, 2>(aHB, mrow, aW1, accB, accA, hA, mrow,
                     sC0, sB12, sWfCur, zvA, (float(*)[2])nullptr, lane, ncol);
        __syncthreads();                                   // S4
        // ---- P4: G2a + E1b -> hB ----
        gemm_u<2, 2>(aHA, mrow, aW2, accA, accB, hB, mrow,
                     sC0, sB12, sWfCur, zvB, (float(*)[2])nullptr, lane, ncol);
        __syncthreads();                                   // S5
        // ---- P5: G2b + E2a dot ----
        float pA[2][2] = {{0.f, 0.f}, {0.f, 0.f}};
        gemm_u<3, 2>(aHB, mrow, aW2, accB, accA, hA, mrow,
                     sC0, sB12, sWfCur, nullptr, pA, lane, ncol);
        reduce_u<2>(pA, sOA, wn, mrow, lane);
        __syncthreads();                                   // S6
        if (tid < 128) {
            float o = sOA[tid] + sOA[128 + tid] + bf[i];
            out[(b0 + tid) * 128 + i] = o;
            *(__half*)(outA + tile_off(tid, i)) = __float2half(o);
        }
        // next-step S0 orders OUT_a writes before G0a
    }
    // ---- tail: E2b for i=127 ----
    {
        float pB[2][2] = {{0.f, 0.f}, {0.f, 0.f}};
        dot_exposed<2>(accB, sWfD + 128, sB12, ncol, lane, pB);   // 127&1 = 1
        __syncthreads();
        reduce_u<2>(pB, sOB, wn, mrow, lane);
        __syncthreads();
        if (tid < 128)
            out[(b0 + 128 + tid) * 128 + 127] = sOB[tid] + sOB[128 + tid] + bf[127];
    }
}

// ============= single-tile kernel: units = two 64-row mt-halves =============
__global__ __launch_bounds__(256, 1)
void gen_single(const float* __restrict__ x,  const float* __restrict__ bi,
                const float* __restrict__ Wf, const float* __restrict__ bf,
                const float* __restrict__ b1, const float* __restrict__ b2,
                float* __restrict__ out, int Bn, int baseRow)
{
    extern __shared__ char sm[];
    const int tid = threadIdx.x, lane = tid & 31, wid = tid >> 5;
    const int wm = wid >> 1, wn = wid & 1;
    const int mrow = wm * 32, ncol = wn * 64;
    const int gr0 = lane >> 2;
    const int rbA = mrow, rbB = mrow + 16;
    const size_t b0 = (size_t)baseRow + (size_t)blockIdx.x * 128;

    const uint32_t smBase = (uint32_t)__cvta_generic_to_shared(sm);
    const uint32_t aOut = smBase + OFF_OUTA;
    const uint32_t aH   = smBase + OFF_HA;
    const uint32_t aWiM = smBase + OFF_WIM, aW1 = smBase + OFF_W1, aW2 = smBase + OFF_W2;
    char* hT = sm + OFF_HA;
    char* outT = sm + OFF_OUTA;
    float2* sC0  = (float2*)(sm + OFF_C0);
    float*  sOA  = (float*)(sm + OFF_C0);      // alias; sC0 dead after P2
    float*  sOB  = (float*)hT;                 // stash; hT dead prev-P5 .. this-P1
    float*  sWfD = (float*)(sm + OFF_WF);
    float2* sB12 = (float2*)(sm + OFF_B12);

    const float4* xg = (const float4*)(x + b0 * 128);
    #pragma unroll
    for (int q = 0; q < 16; q++) {
        int v = (q << 8) + tid;
        float4 f = xg[v];
        int rv = v >> 5, c4 = (v & 31) << 2;
        uint32_t off = tile_off(rv & 127, c4);
        *(__half2*)(outT + off)     = __floats2half2_rn(f.x, f.y);
        *(__half2*)(outT + off + 4) = __floats2half2_rn(f.z, f.w);
    }
    #pragma unroll
    for (int q = 0; q < 8; q++) {
        int v = (q << 8) + tid;
        ((uint4*)(sm + OFF_W1))[v] = ((const uint4*)g_W1h)[v];
        ((uint4*)(sm + OFF_W2))[v] = ((const uint4*)g_W2h)[v];
        cpa16(aWiM + (uint32_t)(v << 4), ((const uint4*)g_WiM) + v);
    }
    asm volatile("cp.async.commit_group;");
    if (tid < 128) sB12[tid] = make_float2(b1[tid], b2[tid]);
    asm volatile("cp.async.wait_group 0;");
    __syncthreads();

    float accA[1][8][4], accB[1][8][4];

    for (int i = 0; i < 128; i++) {
        if (i) { asm volatile("cp.async.wait_group 0;"); __syncthreads(); }  // S0
        if (tid < 128) sWfD[(i & 1) * 128 + tid] = Wf[(i << 7) + tid];
        const float* sWfCur  = sWfD + (i & 1) * 128;
        const float* sWfPrev = sWfD + ((i & 1) ^ 1) * 128;

        // ---- P0: G0(uA) + (i>0: E2(uB) dot of prev step) ----
        float pB[1][2] = {{0.f, 0.f}};
        if (i) {
            gemm_u<3, 1>(aOut, rbA, aWiM, accA, accB, hT, rbB,
                         sC0, sB12, sWfPrev, nullptr, pB, lane, ncol);
            reduce_u<1>(pB, sOB, wn, rbB, lane);
        } else {
            gemm_u<0, 1>(aOut, rbA, aWiM, accA, accB, hT, rbB,
                         sC0, sB12, sWfCur, nullptr, pB, lane, ncol);
        }
        __syncthreads();                                   // S1
        if (i && tid < 128 && ((tid >> 4) & 1) == 1) {
            float o = sOB[tid] + sOB[128 + tid] + bf[i - 1];
            out[(b0 + tid) * 128 + (i - 1)] = o;
            *(__half*)(outT + tile_off(tid, i - 1)) = __float2half(o);
        }
        if (tid < 128) sC0[tid] = make_float2(g_wz[(i << 7) + tid], bi[(i << 7) + tid]);
        __syncthreads();                                   // S1b

        const float* zg = g_zT + (size_t)i * Bn + b0;
        float zvA[2] = { zg[rbA + gr0], zg[rbA + 8 + gr0] };
        float zvB[2] = { zg[rbB + gr0], zg[rbB + 8 + gr0] };

        // ---- P1: G0(uB) + E0(uA) ----
        gemm_u<1, 1>(aOut, rbB, aWiM, accB, accA, hT, rbA,
                     sC0, sB12, sWfCur, zvA, (float(*)[2])nullptr, lane, ncol);
        __syncthreads();                                   // S2
        if (i < 127) {
            const uint4* src = (const uint4*)(g_WiM + (size_t)(i + 1) * 16384);
            #pragma unroll
            for (int q = 0; q < 8; q++) {
                int v = (q << 8) + tid;
                cpa16(aWiM + (uint32_t)(v << 4), src + v);
            }
            asm volatile("cp.async.commit_group;");
        }
        // ---- P2: G1(uA) + E0(uB) ----
        gemm_u<1, 1>(aH, rbA, aW1, accA, accB, hT, rbB,
                     sC0, sB12, sWfCur, zvB, (float(*)[2])nullptr, lane, ncol);
        __syncthreads();                                   // S3
        // ---- P3: G1(uB) + E1(uA) ----
        gemm_u<2, 1>(aH, rbB, aW1, accB, accA, hT, rbA,
                     sC0, sB12, sWfCur, zvA, (float(*)[2])nullptr, lane, ncol);
        __syncthreads();                                   // S4
        // ---- P4: G2(uA) + E1(uB) ----
        gemm_u<2, 1>(aH, rbA, aW2, accA, accB, hT, rbB,
                     sC0, sB12, sWfCur, zvB, (float(*)[2])nullptr, lane, ncol);
        __syncthreads();                                   // S5
        // ---- P5: G2(uB) + E2(uA) dot ----
        float pA[1][2] = {{0.f, 0.f}};
        gemm_u<3, 1>(aH, rbB, aW2, accB, accA, hT, rbA,
                     sC0, sB12, sWfCur, nullptr, pA, lane, ncol);
        reduce_u<1>(pA, sOA, wn, rbA, lane);
        __syncthreads();                                   // S6
        if (tid < 128 && ((tid >> 4) & 1) == 0) {
            float o = sOA[tid] + sOA[128 + tid] + bf[i];
            out[(b0 + tid) * 128 + i] = o;
            *(__half*)(outT + tile_off(tid, i)) = __float2half(o);
        }
    }
    // ---- tail: E2(uB) for i=127 ----
    {
        float pB[1][2] = {{0.f, 0.f}};
        dot_exposed<1>(accB, sWfD + 128, sB12, ncol, lane, pB);
        __syncthreads();
        reduce_u<1>(pB, sOB, wn, rbB, lane);
        __syncthreads();
        if (tid < 128 && ((tid >> 4) & 1) == 1)
            out[(b0 + tid) * 128 + 127] = sOB[tid] + sOB[128 + tid] + bf[127];
    }
}

// ---- host ----
extern "C" void kernel_launch(void* const* d_in, const int* in_sizes, int n_in,
                              void* d_out, int out_size) {
    const float* x  = (const float*)d_in[0];
    const float* z  = (const float*)d_in[1];
    const float* M  = (const float*)d_in[2];
    const float* Wi = (const float*)d_in[3];
    const float* bi = (const float*)d_in[4];
    const float* Wf = (const float*)d_in[5];
    const float* bf = (const float*)d_in[6];
    const float* W1 = (const float*)d_in[7];
    const float* b1 = (const float*)d_in[8];
    const float* W2 = (const float*)d_in[9];
    const float* b2 = (const float*)d_in[10];
    int Bn = in_sizes[0] / 128;

    cudaFuncSetAttribute(gen_pair,   cudaFuncAttributeMaxDynamicSharedMemorySize, SMEM_TOTAL);
    cudaFuncSetAttribute(gen_single, cudaFuncAttributeMaxDynamicSharedMemorySize, SMEM_TOTAL);

    prep_weights<<<130, 256>>>(Wi, M, W1, W2);
    transpose_z<<<dim3(Bn / 32, 4), dim3(32, 8)>>>(z, Bn);

    int tiles = Bn / 128;                       // 1024
    int nPair = ((tiles / 2) / 148) * 148;      // 444 (3 full waves)
    int nSingle = tiles - 2 * nPair;            // 136 (1 partial wave)
    if (nPair > 0)
        gen_pair<<<nPair, 256, SMEM_TOTAL>>>(x, bi, Wf, bf, b1, b2, (float*)d_out, Bn, 0);
    if (nSingle > 0)
        gen_single<<<nSingle, 256, SMEM_TOTAL>>>(x, bi, Wf, bf, b1, b2, (float*)d_out, Bn, nPair * 256);
}

// round 11
// speedup vs baseline: 1.0224x; 1.0224x over previous
#include <cuda_runtime.h>
#include <cuda_fp16.h>
#include <cstdint>

// ---- SMEM layout (bytes): 7 x 32KB unpadded swizzled fp16 tiles + small ----
#define OFF_OUTA 0
#define OFF_OUTB 32768
#define OFF_HA   65536
#define OFF_HB   98304
#define OFF_WIM  131072
#define OFF_W1   163840
#define OFF_W2   196608
#define OFF_C0   229376   // float2 (wz,bi)[128] = 1KB
#define OFF_WF   230400   // float[128]
#define OFF_B12  230912   // float2 (b1,b2)[128] = 1KB
#define SMEM_TOTAL 231936

// ---- device scratch ----
__device__ __half g_WiM[(size_t)128 * 16384];  // per-i swizzled 128x128 fp16 image
__device__ float  g_wz[128 * 128];
__device__ __half g_W1h[16384];                // swizzled image
__device__ __half g_W2h[16384];
__device__ float  g_zT[(size_t)128 * 131072];  // [i][b]

// XOR-swizzled byte offset in a 128x128 fp16 tile (row = 256B)
__host__ __device__ __forceinline__ uint32_t tile_off(int r, int c) {
    return (uint32_t)(r * 256 + ((c * 2) ^ ((r & 7) << 4)));
}

// ---- prologue kernels ----
__global__ void prep_weights(const float* __restrict__ Wi, const float* __restrict__ M,
                             const float* __restrict__ W1, const float* __restrict__ W2) {
    int i = blockIdx.x;
    if (i < 128) {
        const float* Wii = Wi + (size_t)i * 16512;   // 128*129
        for (int v = threadIdx.x; v < 16384; v += blockDim.x) {
            int j = v >> 7, k = v & 127;
            float m = (k == i) ? 0.f : M[k * 128 + i];
            g_WiM[(size_t)i * 16384 + (tile_off(j, k) >> 1)] = __float2half(Wii[j * 129 + k] * m);
        }
        for (int j = threadIdx.x; j < 128; j += blockDim.x)
            g_wz[i * 128 + j] = Wii[j * 129 + 128];
    } else if (i == 128) {
        for (int v = threadIdx.x; v < 16384; v += blockDim.x)
            g_W1h[tile_off(v >> 7, v & 127) >> 1] = __float2half(W1[v]);
    } else {
        for (int v = threadIdx.x; v < 16384; v += blockDim.x)
            g_W2h[tile_off(v >> 7, v & 127) >> 1] = __float2half(W2[v]);
    }
}

__global__ void transpose_z(const float* __restrict__ z, int Bn) {
    __shared__ float t[32][33];
    int b0 = blockIdx.x * 32, i0 = blockIdx.y * 32;
    #pragma unroll
    for (int r = threadIdx.y; r < 32; r += 8)
        t[r][threadIdx.x] = z[(size_t)(b0 + r) * 128 + i0 + threadIdx.x];
    __syncthreads();
    #pragma unroll
    for (int r = threadIdx.y; r < 32; r += 8)
        g_zT[(size_t)(i0 + r) * Bn + b0 + threadIdx.x] = t[threadIdx.x][r];
}

// ---- mma helpers ----
__device__ __forceinline__ void ldsm4(uint32_t addr, uint32_t* r) {
    asm volatile("ldmatrix.sync.aligned.m8n8.x4.shared.b16 {%0,%1,%2,%3},[%4];"
        : "=r"(r[0]), "=r"(r[1]), "=r"(r[2]), "=r"(r[3]) : "r"(addr));
}
__device__ __forceinline__ void mma16816(float* c, const uint32_t* a, const uint32_t* b) {
    asm volatile("mma.sync.aligned.m16n8k16.row.col.f32.f16.f16.f32 "
        "{%0,%1,%2,%3},{%4,%5,%6,%7},{%8,%9},{%0,%1,%2,%3};"
        : "+f"(c[0]), "+f"(c[1]), "+f"(c[2]), "+f"(c[3])
        : "r"(a[0]), "r"(a[1]), "r"(a[2]), "r"(a[3]), "r"(b[0]), "r"(b[1]));
}
__device__ __forceinline__ void cpa16(uint32_t s, const void* g) {
    asm volatile("cp.async.cg.shared.global [%0],[%1],16;" :: "r"(s), "l"(g));
}

// ============ 32x32 warp-tile GEMM + interleaved epilogue chunk of other tile ============
// Warp owns rows [mrow,mrow+32) x cols [ncol,ncol+32). acc[2][4][4].
// EPI: 0 none | 1 relu(accE + z*wz + bi)->H | 2 relu(accE + b1)->H | 3 fc_f dot->p
template<int EPI>
__device__ __forceinline__ void gemm_w(
    uint32_t aTile, uint32_t bBase,
    float (*accG)[4][4], const float (*accE)[4][4],
    char* hEpi,
    const float2* sC0, const float2* sB12, const float* sWfc,
    const float* zv, float (*p)[2],
    int lane, int mrow, int ncol)
{
    #pragma unroll
    for (int mt = 0; mt < 2; mt++)
        #pragma unroll
        for (int nt = 0; nt < 4; nt++)
            #pragma unroll
            for (int c = 0; c < 4; c++) accG[mt][nt][c] = 0.f;

    const int gr0 = lane >> 2, gc0 = 2 * (lane & 3);
    const int rA = mrow + (lane & 15);
    const uint32_t rowA0 = aTile + (uint32_t)(rA * 256);
    const uint32_t xorA = (uint32_t)((rA & 7) << 4);
    const uint32_t cA = (lane & 16) ? 16u : 0u;
    const int rB = ncol + (lane & 7) + ((lane & 16) ? 8 : 0);
    const uint32_t rowW = bBase + (uint32_t)(rB * 256);
    const uint32_t xorB = (uint32_t)((lane & 7) << 4);
    const uint32_t cB = (lane & 8) ? 16u : 0u;
    const uint32_t xrE = (uint32_t)(gr0 << 4);

    #pragma unroll
    for (int ks = 0; ks < 8; ks++) {
        uint32_t offA = ((uint32_t)(ks * 32) + cA) ^ xorA;
        uint32_t offB = ((uint32_t)(ks * 32) + cB) ^ xorB;
        uint32_t a0[4], a1[4], b[8];
        ldsm4(rowA0 + offA, a0);
        ldsm4(rowA0 + 4096 + offA, a1);
        ldsm4(rowW + offB, b);
        ldsm4(rowW + 4096 + offB, b + 4);
        #pragma unroll
        for (int nt = 0; nt < 4; nt++) {
            const uint32_t* bb = b + (nt >> 1) * 4 + (nt & 1) * 2;
            mma16816(accG[0][nt], a0, bb);
            mma16816(accG[1][nt], a1, bb);
        }
        // ---- epilogue chunk of the OTHER tile: (nt = ks>>1, mt = ks&1) ----
        if (EPI == 1 || EPI == 2) {
            const int nt = ks >> 1, mte = ks & 1;
            const int c = ncol + nt * 8 + gc0;
            float x0, x1, za0 = 0.f, za1 = 0.f;
            if (EPI == 1) { float2 t0 = sC0[c], t1 = sC0[c + 1];
                            x0 = t0.y; x1 = t1.y; za0 = t0.x; za1 = t1.x; }
            else          { x0 = sB12[c].x; x1 = sB12[c + 1].x; }
            const uint32_t cb = ((uint32_t)(2 * c)) ^ xrE;
            const int r0 = mrow + mte * 16 + gr0, r1 = r0 + 8;
            float v00 = accE[mte][nt][0], v01 = accE[mte][nt][1];
            float v10 = accE[mte][nt][2], v11 = accE[mte][nt][3];
            if (EPI == 1) {
                const float zlo = zv[mte * 2], zhi = zv[mte * 2 + 1];
                v00 = fmaf(zlo, za0, v00); v01 = fmaf(zlo, za1, v01);
                v10 = fmaf(zhi, za0, v10); v11 = fmaf(zhi, za1, v11);
            }
            v00 = fmaxf(v00 + x0, 0.f); v01 = fmaxf(v01 + x1, 0.f);
            v10 = fmaxf(v10 + x0, 0.f); v11 = fmaxf(v11 + x1, 0.f);
            *(__half2*)(hEpi + r0 * 256 + cb) = __floats2half2_rn(v00, v01);
            *(__half2*)(hEpi + r1 * 256 + cb) = __floats2half2_rn(v10, v11);
        }
        if (EPI == 3) {
            const int nt = ks >> 1, mte = ks & 1;
            const int c = ncol + nt * 8 + gc0;
            const float wf0 = sWfc[c], wf1 = sWfc[c + 1];
            const float q0 = sB12[c].y, q1 = sB12[c + 1].y;
            p[mte][0] = fmaf(fmaxf(accE[mte][nt][0] + q0, 0.f), wf0,
                        fmaf(fmaxf(accE[mte][nt][1] + q1, 0.f), wf1, p[mte][0]));
            p[mte][1] = fmaf(fmaxf(accE[mte][nt][2] + q0, 0.f), wf0,
                        fmaf(fmaxf(accE[mte][nt][3] + q1, 0.f), wf1, p[mte][1]));
        }
    }
}

// exposed epilogue store (single kernel): relu(acc + coef) -> H
template<int MODE>  // 1: z*wz+bi ; 2: +b1
__device__ __forceinline__ void epi_store(const float (*acc)[4][4], char* hT,
    const float2* sC0, const float2* sB12, const float* zv,
    int lane, int mrow, int ncol)
{
    const int gr0 = lane >> 2, gc0 = 2 * (lane & 3);
    const uint32_t xrE = (uint32_t)(gr0 << 4);
    #pragma unroll
    for (int nt = 0; nt < 4; nt++) {
        const int c = ncol + nt * 8 + gc0;
        float x0, x1, za0 = 0.f, za1 = 0.f;
        if (MODE == 1) { float2 t0 = sC0[c], t1 = sC0[c + 1];
                         x0 = t0.y; x1 = t1.y; za0 = t0.x; za1 = t1.x; }
        else           { x0 = sB12[c].x; x1 = sB12[c + 1].x; }
        const uint32_t cb = ((uint32_t)(2 * c)) ^ xrE;
        #pragma unroll
        for (int mt = 0; mt < 2; mt++) {
            const int r0 = mrow + mt * 16 + gr0, r1 = r0 + 8;
            float v00 = acc[mt][nt][0], v01 = acc[mt][nt][1];
            float v10 = acc[mt][nt][2], v11 = acc[mt][nt][3];
            if (MODE == 1) {
                const float zlo = zv[mt * 2], zhi = zv[mt * 2 + 1];
                v00 = fmaf(zlo, za0, v00); v01 = fmaf(zlo, za1, v01);
                v10 = fmaf(zhi, za0, v10); v11 = fmaf(zhi, za1, v11);
            }
            v00 = fmaxf(v00 + x0, 0.f); v01 = fmaxf(v01 + x1, 0.f);
            v10 = fmaxf(v10 + x0, 0.f); v11 = fmaxf(v11 + x1, 0.f);
            *(__half2*)(hT + r0 * 256 + cb) = __floats2half2_rn(v00, v01);
            *(__half2*)(hT + r1 * 256 + cb) = __floats2half2_rn(v10, v11);
        }
    }
}

// exposed fc_f dot
__device__ __forceinline__ void dot_exposed(const float (*acc)[4][4],
    const float* sWfc, const float2* sB12, int ncol, int lane, float (*p)[2]) {
    const int gc0 = 2 * (lane & 3);
    #pragma unroll
    for (int nt = 0; nt < 4; nt++) {
        const int c = ncol + nt * 8 + gc0;
        const float wf0 = sWfc[c], wf1 = sWfc[c + 1];
        const float q0 = sB12[c].y, q1 = sB12[c + 1].y;
        #pragma unroll
        for (int mt = 0; mt < 2; mt++) {
            p[mt][0] = fmaf(fmaxf(acc[mt][nt][0] + q0, 0.f), wf0,
                       fmaf(fmaxf(acc[mt][nt][1] + q1, 0.f), wf1, p[mt][0]));
            p[mt][1] = fmaf(fmaxf(acc[mt][nt][2] + q0, 0.f), wf0,
                       fmaf(fmaxf(acc[mt][nt][3] + q1, 0.f), wf1, p[mt][1]));
        }
    }
}

// reduce fc_f partials into sO[wn*128 + row] (wn 0..3)
__device__ __forceinline__ void reduce_w(float (*p)[2], float* sO, int wn, int mrow, int lane) {
    const int gr0 = lane >> 2;
    #pragma unroll
    for (int mt = 0; mt < 2; mt++)
        #pragma unroll
        for (int hh = 0; hh < 2; hh++) {
            float v = p[mt][hh];
            v += __shfl_xor_sync(0xffffffffu, v, 1);
            v += __shfl_xor_sync(0xffffffffu, v, 2);
            if ((lane & 3) == 0)
                sO[wn * 128 + mrow + mt * 16 + hh * 8 + gr0] = v;
        }
}

// ==================== pair kernel: 512 threads, 16 warps (4x4), 2 tiles ====================
__global__ __launch_bounds__(512, 1)
void gen_pair(const float* __restrict__ x,  const float* __restrict__ bi,
              const float* __restrict__ Wf, const float* __restrict__ bf,
              const float* __restrict__ b1, const float* __restrict__ b2,
              float* __restrict__ out, int Bn, int baseRow)
{
    extern __shared__ char sm[];
    const int tid = threadIdx.x, lane = tid & 31, wid = tid >> 5;
    const int wm = wid >> 2, wn = wid & 3;
    const int mrow = wm * 32, ncol = wn * 32;
    const int gr0 = lane >> 2;
    const size_t b0 = (size_t)baseRow + (size_t)blockIdx.x * 256;

    const uint32_t smBase = (uint32_t)__cvta_generic_to_shared(sm);
    const uint32_t aOutA = smBase + OFF_OUTA, aOutB = smBase + OFF_OUTB;
    const uint32_t aHA = smBase + OFF_HA, aHB = smBase + OFF_HB;
    const uint32_t aWiM = smBase + OFF_WIM, aW1 = smBase + OFF_W1, aW2 = smBase + OFF_W2;
    char* hA = sm + OFF_HA; char* hB = sm + OFF_HB;
    char* outA = sm + OFF_OUTA; char* outB = sm + OFF_OUTB;
    float* sOA = (float*)hA;                   // stash: hA dead after G2a (S5)
    float* sOB = (float*)hB;                   // stash: hB dead after G2b (S6)
    float2* sC0  = (float2*)(sm + OFF_C0);
    float*  sWf  = (float*)(sm + OFF_WF);
    float2* sB12 = (float2*)(sm + OFF_B12);

    // ---- stage x into both tiles ----
    const float4* xg = (const float4*)(x + b0 * 128);
    #pragma unroll
    for (int q = 0; q < 16; q++) {
        int v = (q << 9) + tid;
        float4 f = xg[v];
        int rv = v >> 5, c4 = (v & 31) << 2;
        uint32_t off = tile_off(rv & 127, c4);
        char* base = sm + ((rv >> 7) ? OFF_OUTB : OFF_OUTA);
        *(__half2*)(base + off)     = __floats2half2_rn(f.x, f.y);
        *(__half2*)(base + off + 4) = __floats2half2_rn(f.z, f.w);
    }
    #pragma unroll
    for (int q = 0; q < 4; q++) {
        int v = (q << 9) + tid;
        ((uint4*)(sm + OFF_W1))[v] = ((const uint4*)g_W1h)[v];
        ((uint4*)(sm + OFF_W2))[v] = ((const uint4*)g_W2h)[v];
        cpa16(aWiM + (uint32_t)(v << 4), ((const uint4*)g_WiM) + v);
    }
    asm volatile("cp.async.commit_group;");
    if (tid < 128) sB12[tid] = make_float2(b1[tid], b2[tid]);
    asm volatile("cp.async.wait_group 0;");
    __syncthreads();

    float accA[2][4][4], accB[2][4][4];
    float pdum[2][2];

    for (int i = 0; i < 128; i++) {
        if (tid < 128) {
            sC0[tid] = make_float2(g_wz[(i << 7) + tid], bi[(i << 7) + tid]);
        } else if (tid < 256) {
            sWf[tid - 128] = Wf[(i << 7) + tid - 128];
        }
        const float bfi = bf[i];
        const float* zg = g_zT + (size_t)i * Bn + b0;
        const int zr = mrow + gr0;
        float zvA[4] = { zg[zr], zg[zr + 8], zg[zr + 16], zg[zr + 24] };
        float zvB[4] = { zg[128 + zr], zg[136 + zr], zg[144 + zr], zg[152 + zr] };

        // P0: G0a (pure mma)
        gemm_w<0>(aOutA, aWiM, accA, accA, hA, sC0, sB12, sWf,
                  zvA, pdum, lane, mrow, ncol);
        __syncthreads();                                   // S1: staging visible

        // P1: G0b + E0a -> hA
        gemm_w<1>(aOutB, aWiM, accB, accA, hA, sC0, sB12, sWf,
                  zvA, pdum, lane, mrow, ncol);
        __syncthreads();                                   // S2: WiM reads done; hA ready

        if (i < 127) {                                     // prefetch WiM(i+1)
            const uint4* src = (const uint4*)(g_WiM + (size_t)(i + 1) * 16384);
            #pragma unroll
            for (int q = 0; q < 4; q++) {
                int v = (q << 9) + tid;
                cpa16(aWiM + (uint32_t)(v << 4), src + v);
            }
            asm volatile("cp.async.commit_group;");
        }

        // P2: G1a (reads hA) + E0b -> hB
        gemm_w<1>(aHA, aW1, accA, accB, hB, sC0, sB12, sWf,
                  zvB, pdum, lane, mrow, ncol);
        __syncthreads();                                   // S3: hB ready

        // P3: G1b (reads hB) + E1a -> hA
        gemm_w<2>(aHB, aW1, accB, accA, hA, sC0, sB12, sWf,
                  zvA, pdum, lane, mrow, ncol);
        __syncthreads();                                   // S4

        // P4: G2a (reads hA) + E1b -> hB
        gemm_w<2>(aHA, aW2, accA, accB, hB, sC0, sB12, sWf,
                  zvB, pdum, lane, mrow, ncol);
        __syncthreads();                                   // S5: hA dead (G2a reads done)

        // P5: G2b (reads hB) + E2a dot -> reduce into sOA (stash in dead hA)
        float pA[2][2] = {{0.f, 0.f}, {0.f, 0.f}};
        gemm_w<3>(aHB, aW2, accB, accA, hA, sC0, sB12, sWf,
                  zvA, pA, lane, mrow, ncol);
        reduce_w(pA, sOA, wn, mrow, lane);
        __syncthreads();                                   // S6: sOA visible; hB dead

        // P6: final-a write + E2b dot (exposed)
        float pB[2][2] = {{0.f, 0.f}, {0.f, 0.f}};
        dot_exposed(accB, sWf, sB12, ncol, lane, pB);
        if (tid < 128) {
            float o = sOA[tid] + sOA[128 + tid] + sOA[256 + tid] + sOA[384 + tid] + bfi;
            out[(b0 + tid) * 128 + i] = o;
            *(__half*)(outA + tile_off(tid, i)) = __float2half(o);
        }
        __syncthreads();                                   // S7
        reduce_w(pB, sOB, wn, mrow, lane);
        if (i < 127) asm volatile("cp.async.wait_group 0;");
        __syncthreads();                                   // S8: sOB + WiM ready
        if (tid < 128) {
            float o = sOB[tid] + sOB[128 + tid] + sOB[256 + tid] + sOB[384 + tid] + bfi;
            out[(b0 + 128 + tid) * 128 + i] = o;
            *(__half*)(outB + tile_off(tid, i)) = __float2half(o);
        }
        __syncthreads();                                   // S9: OUT cols settled
    }
}

// ============= single-tile kernel: 512 threads, 16 warps, plain phases =============
__global__ __launch_bounds__(512, 1)
void gen_single(const float* __restrict__ x,  const float* __restrict__ bi,
                const float* __restrict__ Wf, const float* __restrict__ bf,
                const float* __restrict__ b1, const float* __restrict__ b2,
                float* __restrict__ out, int Bn, int baseRow)
{
    extern __shared__ char sm[];
    const int tid = threadIdx.x, lane = tid & 31, wid = tid >> 5;
    const int wm = wid >> 2, wn = wid & 3;
    const int mrow = wm * 32, ncol = wn * 32;
    const int gr0 = lane >> 2;
    const size_t b0 = (size_t)baseRow + (size_t)blockIdx.x * 128;

    const uint32_t smBase = (uint32_t)__cvta_generic_to_shared(sm);
    const uint32_t aOut = smBase + OFF_OUTA;
    const uint32_t aH   = smBase + OFF_HA;
    const uint32_t aWiM = smBase + OFF_WIM, aW1 = smBase + OFF_W1, aW2 = smBase + OFF_W2;
    char* hT = sm + OFF_HA;
    char* outT = sm + OFF_OUTA;
    float* sO = (float*)hT;                    // stash: hT dead after G2 reads
    float2* sC0  = (float2*)(sm + OFF_C0);
    float*  sWf  = (float*)(sm + OFF_WF);
    float2* sB12 = (float2*)(sm + OFF_B12);

    const float4* xg = (const float4*)(x + b0 * 128);
    #pragma unroll
    for (int q = 0; q < 8; q++) {
        int v = (q << 9) + tid;
        float4 f = xg[v];
        int rv = v >> 5, c4 = (v & 31) << 2;
        uint32_t off = tile_off(rv & 127, c4);
        *(__half2*)(outT + off)     = __floats2half2_rn(f.x, f.y);
        *(__half2*)(outT + off + 4) = __floats2half2_rn(f.z, f.w);
    }
    #pragma unroll
    for (int q = 0; q < 4; q++) {
        int v = (q << 9) + tid;
        ((uint4*)(sm + OFF_W1))[v] = ((const uint4*)g_W1h)[v];
        ((uint4*)(sm + OFF_W2))[v] = ((const uint4*)g_W2h)[v];
        cpa16(aWiM + (uint32_t)(v << 4), ((const uint4*)g_WiM) + v);
    }
    asm volatile("cp.async.commit_group;");
    if (tid < 128) sB12[tid] = make_float2(b1[tid], b2[tid]);
    asm volatile("cp.async.wait_group 0;");
    __syncthreads();

    float acc[2][4][4];
    float pdum[2][2];

    for (int i = 0; i < 128; i++) {
        if (tid < 128) {
            sC0[tid] = make_float2(g_wz[(i << 7) + tid], bi[(i << 7) + tid]);
        } else if (tid < 256) {
            sWf[tid - 128] = Wf[(i << 7) + tid - 128];
        }
        const float bfi = bf[i];
        const float* zg = g_zT + (size_t)i * Bn + b0;
        const int zr = mrow + gr0;
        float zv[4] = { zg[zr], zg[zr + 8], zg[zr + 16], zg[zr + 24] };
        __syncthreads();

        // G0
        gemm_w<0>(aOut, aWiM, acc, acc, hT, sC0, sB12, sWf, zv, pdum, lane, mrow, ncol);
        __syncthreads();
        if (i < 127) {
            const uint4* src = (const uint4*)(g_WiM + (size_t)(i + 1) * 16384);
            #pragma unroll
            for (int q = 0; q < 4; q++) {
                int v = (q << 9) + tid;
                cpa16(aWiM + (uint32_t)(v << 4), src + v);
            }
            asm volatile("cp.async.commit_group;");
        }
        // E0 -> H
        epi_store<1>(acc, hT, sC0, sB12, zv, lane, mrow, ncol);
        __syncthreads();
        // G1
        gemm_w<0>(aH, aW1, acc, acc, hT, sC0, sB12, sWf, zv, pdum, lane, mrow, ncol);
        __syncthreads();
        // E1 -> H (in place)
        epi_store<2>(acc, hT, sC0, sB12, zv, lane, mrow, ncol);
        __syncthreads();
        // G2
        gemm_w<0>(aH, aW2, acc, acc, hT, sC0, sB12, sWf, zv, pdum, lane, mrow, ncol);
        // E2 dot
        float p[2][2] = {{0.f, 0.f}, {0.f, 0.f}};
        dot_exposed(acc, sWf, sB12, ncol, lane, p);
        __syncthreads();                       // hT dead (all G2 reads done)
        reduce_w(p, sO, wn, mrow, lane);
        __syncthreads();
        if (tid < 128) {
            float o = sO[tid] + sO[128 + tid] + sO[256 + tid] + sO[384 + tid] + bfi;
            out[(b0 + tid) * 128 + i] = o;
            *(__half*)(outT + tile_off(tid, i)) = __float2half(o);
        }
        if (i < 127) asm volatile("cp.async.wait_group 0;");
        __syncthreads();
    }
}

// ---- host ----
extern "C" void kernel_launch(void* const* d_in, const int* in_sizes, int n_in,
                              void* d_out, int out_size) {
    const float* x  = (const float*)d_in[0];
    const float* z  = (const float*)d_in[1];
    const float* M  = (const float*)d_in[2];
    const float* Wi = (const float*)d_in[3];
    const float* bi = (const float*)d_in[4];
    const float* Wf = (const float*)d_in[5];
    const float* bf = (const float*)d_in[6];
    const float* W1 = (const float*)d_in[7];
    const float* b1 = (const float*)d_in[8];
    const float* W2 = (const float*)d_in[9];
    const float* b2 = (const float*)d_in[10];
    int Bn = in_sizes[0] / 128;

    cudaFuncSetAttribute(gen_pair,   cudaFuncAttributeMaxDynamicSharedMemorySize, SMEM_TOTAL);
    cudaFuncSetAttribute(gen_single, cudaFuncAttributeMaxDynamicSharedMemorySize, SMEM_TOTAL);

    prep_weights<<<130, 256>>>(Wi, M, W1, W2);
    transpose_z<<<dim3(Bn / 32, 4), dim3(32, 8)>>>(z, Bn);

    int tiles = Bn / 128;                       // 1024
    int nPair = ((tiles / 2) / 148) * 148;      // 444 (3 full waves)
    int nSingle = tiles - 2 * nPair;            // 136 (1 partial wave)
    if (nPair > 0)
        gen_pair<<<nPair, 512, SMEM_TOTAL>>>(x, bi, Wf, bf, b1, b2, (float*)d_out, Bn, 0);
    if (nSingle > 0)
        gen_single<<<nSingle, 512, SMEM_TOTAL>>>(x, bi, Wf, bf, b1, b2, (float*)d_out, Bn, nPair * 256);
}

// round 12
// speedup vs baseline: 1.1261x; 1.1014x over previous
#include <cuda_runtime.h>
#include <cuda_fp16.h>
#include <cstdint>

// ---- SMEM layout (bytes) ----
#define OFF_OUTA 0
#define OFF_OUTB 32768
#define OFF_WIM  65536
#define OFF_W1   98304
#define OFF_W2   131072
#define OFF_C0   163840   // float2[2][128] double-buffered (wz,bi)
#define OFF_WFD  165888   // float[2][128] double-buffered Wf
#define OFF_B12  166912   // float2[128] (b1,b2)
#define SMEM_TOTAL 167936

// ---- device scratch ----
__device__ __half g_WiM[(size_t)128 * 16384];  // per-i swizzled 128x128 fp16 image
__device__ float  g_wz[128 * 128];
__device__ __half g_W1h[16384];                // swizzled image
__device__ __half g_W2h[16384];
__device__ float  g_zT[(size_t)128 * 131072];  // [i][b]

// XOR-swizzled byte offset in a 128x128 fp16 tile (row = 256B)
__host__ __device__ __forceinline__ uint32_t tile_off(int r, int c) {
    return (uint32_t)(r * 256 + ((c * 2) ^ ((r & 7) << 4)));
}

// ---- prologue kernels ----
__global__ void prep_weights(const float* __restrict__ Wi, const float* __restrict__ M,
                             const float* __restrict__ W1, const float* __restrict__ W2) {
    int i = blockIdx.x;
    if (i < 128) {
        const float* Wii = Wi + (size_t)i * 16512;   // 128*129
        for (int v = threadIdx.x; v < 16384; v += blockDim.x) {
            int j = v >> 7, k = v & 127;
            float m = (k == i) ? 0.f : M[k * 128 + i];
            g_WiM[(size_t)i * 16384 + (tile_off(j, k) >> 1)] = __float2half(Wii[j * 129 + k] * m);
        }
        for (int j = threadIdx.x; j < 128; j += blockDim.x)
            g_wz[i * 128 + j] = Wii[j * 129 + 128];
    } else if (i == 128) {
        for (int v = threadIdx.x; v < 16384; v += blockDim.x)
            g_W1h[tile_off(v >> 7, v & 127) >> 1] = __float2half(W1[v]);
    } else {
        for (int v = threadIdx.x; v < 16384; v += blockDim.x)
            g_W2h[tile_off(v >> 7, v & 127) >> 1] = __float2half(W2[v]);
    }
}

__global__ void transpose_z(const float* __restrict__ z, int Bn) {
    __shared__ float t[32][33];
    int b0 = blockIdx.x * 32, i0 = blockIdx.y * 32;
    #pragma unroll
    for (int r = threadIdx.y; r < 32; r += 8)
        t[r][threadIdx.x] = z[(size_t)(b0 + r) * 128 + i0 + threadIdx.x];
    __syncthreads();
    #pragma unroll
    for (int r = threadIdx.y; r < 32; r += 8)
        g_zT[(size_t)(i0 + r) * Bn + b0 + threadIdx.x] = t[threadIdx.x][r];
}

// ---- mma helpers ----
__device__ __forceinline__ void ldsm4(uint32_t addr, uint32_t* r) {
    asm volatile("ldmatrix.sync.aligned.m8n8.x4.shared.b16 {%0,%1,%2,%3},[%4];"
        : "=r"(r[0]), "=r"(r[1]), "=r"(r[2]), "=r"(r[3]) : "r"(addr));
}
__device__ __forceinline__ void mma16816(float* c, const uint32_t* a, const uint32_t* b) {
    asm volatile("mma.sync.aligned.m16n8k16.row.col.f32.f16.f16.f32 "
        "{%0,%1,%2,%3},{%4,%5,%6,%7},{%8,%9},{%0,%1,%2,%3};"
        : "+f"(c[0]), "+f"(c[1]), "+f"(c[2]), "+f"(c[3])
        : "r"(a[0]), "r"(a[1]), "r"(a[2]), "r"(a[3]), "r"(b[0]), "r"(b[1]));
}
__device__ __forceinline__ void cpa16(uint32_t s, const void* g) {
    asm volatile("cp.async.cg.shared.global [%0],[%1],16;" :: "r"(s), "l"(g));
}

// ---- GEMM over full N=128, A from smem (G0). Warp rows: mrowT..mrowT+16*NMT ----
template<int NMT>
__device__ __forceinline__ void gemm_s(uint32_t aTile, int mrowT, uint32_t bBase,
                                       float (*acc)[16][4], int lane) {
    #pragma unroll
    for (int mt = 0; mt < NMT; mt++)
        #pragma unroll
        for (int nb = 0; nb < 16; nb++)
            #pragma unroll
            for (int c = 0; c < 4; c++) acc[mt][nb][c] = 0.f;

    const uint32_t xorA = (uint32_t)((lane & 7) << 4);
    const uint32_t cA = (lane & 16) ? 16u : 0u;
    uint32_t rowA[NMT];
    #pragma unroll
    for (int mt = 0; mt < NMT; mt++)
        rowA[mt] = aTile + (uint32_t)((mrowT + mt * 16 + (lane & 15)) * 256);
    const uint32_t rowW = bBase + (uint32_t)((((lane & 7) + ((lane & 16) ? 8 : 0))) * 256);
    const uint32_t xorB = (uint32_t)((lane & 7) << 4);
    const uint32_t cB = (lane & 8) ? 16u : 0u;

    #pragma unroll
    for (int ks = 0; ks < 8; ks++) {
        uint32_t offA = ((uint32_t)(ks * 32) + cA) ^ xorA;
        uint32_t offB = ((uint32_t)(ks * 32) + cB) ^ xorB;
        uint32_t a[NMT][4], b[32];
        #pragma unroll
        for (int mt = 0; mt < NMT; mt++) ldsm4(rowA[mt] + offA, a[mt]);
        #pragma unroll
        for (int q = 0; q < 8; q++) ldsm4(rowW + (uint32_t)(q * 4096) + offB, b + 4 * q);
        #pragma unroll
        for (int nb = 0; nb < 16; nb++)
            #pragma unroll
            for (int mt = 0; mt < NMT; mt++)
                mma16816(acc[mt][nb], a[mt], b + 2 * nb);
    }
}

// ---- GEMM over full N=128, A from registers (hf: C->A fragment identity) ----
template<int NMT>
__device__ __forceinline__ void gemm_r(const uint32_t (*hf)[32], uint32_t bBase,
                                       float (*acc)[16][4], int lane) {
    #pragma unroll
    for (int mt = 0; mt < NMT; mt++)
        #pragma unroll
        for (int nb = 0; nb < 16; nb++)
            #pragma unroll
            for (int c = 0; c < 4; c++) acc[mt][nb][c] = 0.f;

    const uint32_t rowW = bBase + (uint32_t)((((lane & 7) + ((lane & 16) ? 8 : 0))) * 256);
    const uint32_t xorB = (uint32_t)((lane & 7) << 4);
    const uint32_t cB = (lane & 8) ? 16u : 0u;

    #pragma unroll
    for (int ks = 0; ks < 8; ks++) {
        uint32_t offB = ((uint32_t)(ks * 32) + cB) ^ xorB;
        uint32_t b[32];
        #pragma unroll
        for (int q = 0; q < 8; q++) ldsm4(rowW + (uint32_t)(q * 4096) + offB, b + 4 * q);
        #pragma unroll
        for (int nb = 0; nb < 16; nb++)
            #pragma unroll
            for (int mt = 0; mt < NMT; mt++)
                mma16816(acc[mt][nb], &hf[mt][4 * ks], b + 2 * nb);
    }
}

// ---- E0/E1: relu(acc + coef) -> fp16 A-fragments in registers ----
// MODE 1: coef = z*wz + bi (sC float2 = (wz,bi)) ; MODE 2: coef = b1 (sB12[].x)
template<int NMT, int MODE>
__device__ __forceinline__ void epi_cvt(const float (*acc)[16][4], uint32_t (*hf)[32],
                                        const float2* sC, const float2* sB12,
                                        const float* zl, int lane) {
    const int gc0 = 2 * (lane & 3);
    #pragma unroll
    for (int nb = 0; nb < 16; nb++) {
        const int c = 8 * nb + gc0;
        float x0, x1, za0 = 0.f, za1 = 0.f;
        if (MODE == 1) { float2 t0 = sC[c], t1 = sC[c + 1];
                         x0 = t0.y; x1 = t1.y; za0 = t0.x; za1 = t1.x; }
        else           { x0 = sB12[c].x; x1 = sB12[c + 1].x; }
        #pragma unroll
        for (int mt = 0; mt < NMT; mt++) {
            float v0 = acc[mt][nb][0], v1 = acc[mt][nb][1];
            float v2 = acc[mt][nb][2], v3 = acc[mt][nb][3];
            if (MODE == 1) {
                const float zlo = zl[2 * mt], zhi = zl[2 * mt + 1];
                v0 = fmaf(zlo, za0, v0); v1 = fmaf(zlo, za1, v1);
                v2 = fmaf(zhi, za0, v2); v3 = fmaf(zhi, za1, v3);
            }
            v0 = fmaxf(v0 + x0, 0.f); v1 = fmaxf(v1 + x1, 0.f);
            v2 = fmaxf(v2 + x0, 0.f); v3 = fmaxf(v3 + x1, 0.f);
            __half2 lo = __floats2half2_rn(v0, v1), hi = __floats2half2_rn(v2, v3);
            hf[mt][2 * nb]     = *(uint32_t*)&lo;
            hf[mt][2 * nb + 1] = *(uint32_t*)&hi;
        }
    }
}

// ==================== main kernel (NT tiles: warps [0,4NT) ) ====================
template<int NT>
__global__ __launch_bounds__(256, 1)
void gen_main(const float* __restrict__ x,  const float* __restrict__ bi,
              const float* __restrict__ Wf, const float* __restrict__ bf,
              const float* __restrict__ b1, const float* __restrict__ b2,
              float* __restrict__ out, int Bn, int baseRow)
{
    extern __shared__ char sm[];
    const int tid = threadIdx.x, lane = tid & 31, wid = tid >> 5;
    const int gr0 = lane >> 2, gc0 = 2 * (lane & 3);
    // NT==2: warps 0-3 -> tile A (32 rows each); warps 4-7 -> tile B.
    // NT==1: 8 warps x 16 rows of tile A.
    const int NMT = (NT == 2) ? 2 : 1;
    const int tileSel = (NT == 2) ? (wid >> 2) : 0;
    const int mrowT = (NT == 2) ? ((wid & 3) * 32) : (wid * 16);
    const size_t b0 = (size_t)baseRow + (size_t)blockIdx.x * (128 * NT);
    const size_t bT = b0 + (size_t)(tileSel << 7);

    const uint32_t smBase = (uint32_t)__cvta_generic_to_shared(sm);
    const uint32_t aOut = smBase + (tileSel ? OFF_OUTB : OFF_OUTA);
    char* outT = sm + (tileSel ? OFF_OUTB : OFF_OUTA);
    const uint32_t aWiM = smBase + OFF_WIM, aW1 = smBase + OFF_W1, aW2 = smBase + OFF_W2;
    float2* sC0D = (float2*)(sm + OFF_C0);    // [2][128]
    float*  sWfD = (float*)(sm + OFF_WFD);    // [2][128]
    float2* sB12 = (float2*)(sm + OFF_B12);

    // ---- stage x into tiles (fp16, swizzled) ----
    const float4* xg = (const float4*)(x + b0 * 128);
    #pragma unroll
    for (int q = 0; q < 16 * NT; q++) {
        int v = (q << 8) + tid;
        float4 f = xg[v];
        int rv = v >> 5, c4 = (v & 31) << 2;
        uint32_t off = tile_off(rv & 127, c4);
        char* base = sm + ((rv >> 7) ? OFF_OUTB : OFF_OUTA);
        *(__half2*)(base + off)     = __floats2half2_rn(f.x, f.y);
        *(__half2*)(base + off + 4) = __floats2half2_rn(f.z, f.w);
    }
    // ---- stage W1/W2 + WiM(0) + coeffs(0) ----
    #pragma unroll
    for (int q = 0; q < 8; q++) {
        int v = (q << 8) + tid;
        ((uint4*)(sm + OFF_W1))[v] = ((const uint4*)g_W1h)[v];
        ((uint4*)(sm + OFF_W2))[v] = ((const uint4*)g_W2h)[v];
        cpa16(aWiM + (uint32_t)(v << 4), ((const uint4*)g_WiM) + v);
    }
    asm volatile("cp.async.commit_group;");
    if (tid < 128) {
        sB12[tid] = make_float2(b1[tid], b2[tid]);
        sC0D[tid] = make_float2(g_wz[tid], bi[tid]);   // buf 0, step 0
        sWfD[tid] = Wf[tid];
    }
    asm volatile("cp.async.wait_group 0;");
    __syncthreads();

    float acc[(NT == 2) ? 2 : 1][16][4];
    uint32_t hf[(NT == 2) ? 2 : 1][32];

    for (int i = 0; i < 128; i++) {
        // S_A: WiM(i) complete+visible; coeffs(i) visible; prev col writes visible
        if (i) { asm volatile("cp.async.wait_group 0;"); __syncthreads(); }

        // stage coeffs for i+1 into buf (i+1)&1 (safe: all E-reads of this buf done pre-barrier)
        if (i < 127) {
            if (tid < 128)
                sC0D[(((i + 1) & 1) << 7) + tid] =
                    make_float2(g_wz[((i + 1) << 7) + tid], bi[((i + 1) << 7) + tid]);
            else
                sWfD[(((i + 1) & 1) << 7) + tid - 128] = Wf[((i + 1) << 7) + tid - 128];
        }
        const float2* sC0w = sC0D + ((i & 1) << 7);
        const float*  sWfw = sWfD + ((i & 1) << 7);
        const float bfi = bf[i];

        // ---- G0: acc = OUT_tile @ WiM^T (full N=128 for this warp's rows) ----
        gemm_s<(NT == 2) ? 2 : 1>(aOut, mrowT, aWiM, acc, lane);
        __syncthreads();                        // S_B: all WiM reads done
        if (i < 127) {                          // prefetch WiM(i+1)
            const uint4* src = (const uint4*)(g_WiM + (size_t)(i + 1) * 16384);
            #pragma unroll
            for (int q = 0; q < 8; q++) {
                int v = (q << 8) + tid;
                cpa16(aWiM + (uint32_t)(v << 4), src + v);
            }
            asm volatile("cp.async.commit_group;");
        }

        // ---- E0 (regs): h1 = relu(acc + z*wz + bi) -> hf ----
        float zl[(NT == 2) ? 4 : 2];
        {
            const float* zg = g_zT + (size_t)i * Bn + bT;
            #pragma unroll
            for (int k = 0; k < ((NT == 2) ? 4 : 2); k++)
                zl[k] = zg[mrowT + (k >> 1) * 16 + (k & 1) * 8 + gr0];
        }
        epi_cvt<(NT == 2) ? 2 : 1, 1>(acc, hf, sC0w, sB12, zl, lane);

        // ---- G1: acc = h1 @ W1^T (A from regs) ----
        gemm_r<(NT == 2) ? 2 : 1>(hf, aW1, acc, lane);
        // ---- E1 (regs): h2 = relu(acc + b1) -> hf ----
        epi_cvt<(NT == 2) ? 2 : 1, 2>(acc, hf, sC0w, sB12, zl, lane);
        // ---- G2: acc = h2 @ W2^T ----
        gemm_r<(NT == 2) ? 2 : 1>(hf, aW2, acc, lane);

        // ---- E2: o = relu(acc + b2) @ Wf + bf ; warp owns full rows ----
        float p0[(NT == 2) ? 2 : 1], p1[(NT == 2) ? 2 : 1];
        #pragma unroll
        for (int mt = 0; mt < NMT; mt++) { p0[mt] = 0.f; p1[mt] = 0.f; }
        #pragma unroll
        for (int nb = 0; nb < 16; nb++) {
            const int c = 8 * nb + gc0;
            const float wf0 = sWfw[c], wf1 = sWfw[c + 1];
            const float q0 = sB12[c].y, q1 = sB12[c + 1].y;
            #pragma unroll
            for (int mt = 0; mt < NMT; mt++) {
                p0[mt] = fmaf(fmaxf(acc[mt][nb][0] + q0, 0.f), wf0,
                         fmaf(fmaxf(acc[mt][nb][1] + q1, 0.f), wf1, p0[mt]));
                p1[mt] = fmaf(fmaxf(acc[mt][nb][2] + q0, 0.f), wf0,
                         fmaf(fmaxf(acc[mt][nb][3] + q1, 0.f), wf1, p1[mt]));
            }
        }
        #pragma unroll
        for (int mt = 0; mt < NMT; mt++) {
            p0[mt] += __shfl_xor_sync(0xffffffffu, p0[mt], 1);
            p0[mt] += __shfl_xor_sync(0xffffffffu, p0[mt], 2);
            p1[mt] += __shfl_xor_sync(0xffffffffu, p1[mt], 1);
            p1[mt] += __shfl_xor_sync(0xffffffffu, p1[mt], 2);
        }
        if ((lane & 3) == 0) {
            #pragma unroll
            for (int mt = 0; mt < NMT; mt++) {
                int r = mrowT + mt * 16 + gr0;
                float o0 = p0[mt] + bfi, o1 = p1[mt] + bfi;
                out[(bT + r) * 128 + i] = o0;
                out[(bT + r + 8) * 128 + i] = o1;
                *(__half*)(outT + tile_off(r, i)) = __float2half(o0);
                *(__half*)(outT + tile_off(r + 8, i)) = __float2half(o1);
            }
        }
        __syncwarp();   // own-row smem writes visible to own warp's next G0 ldsm
    }
}

// ---- host ----
extern "C" void kernel_launch(void* const* d_in, const int* in_sizes, int n_in,
                              void* d_out, int out_size) {
    const float* x  = (const float*)d_in[0];
    const float* z  = (const float*)d_in[1];
    const float* M  = (const float*)d_in[2];
    const float* Wi = (const float*)d_in[3];
    const float* bi = (const float*)d_in[4];
    const float* Wf = (const float*)d_in[5];
    const float* bf = (const float*)d_in[6];
    const float* W1 = (const float*)d_in[7];
    const float* b1 = (const float*)d_in[8];
    const float* W2 = (const float*)d_in[9];
    const float* b2 = (const float*)d_in[10];
    int Bn = in_sizes[0] / 128;

    cudaFuncSetAttribute(gen_main<2>, cudaFuncAttributeMaxDynamicSharedMemorySize, SMEM_TOTAL);
    cudaFuncSetAttribute(gen_main<1>, cudaFuncAttributeMaxDynamicSharedMemorySize, SMEM_TOTAL);

    prep_weights<<<130, 256>>>(Wi, M, W1, W2);
    transpose_z<<<dim3(Bn / 32, 4), dim3(32, 8)>>>(z, Bn);

    int tiles = Bn / 128;                       // 1024
    int nPair = ((tiles / 2) / 148) * 148;      // 444 (3 full waves)
    int nSingle = tiles - 2 * nPair;            // 136 (1 partial wave)
    if (nPair > 0)
        gen_main<2><<<nPair, 256, SMEM_TOTAL>>>(x, bi, Wf, bf, b1, b2, (float*)d_out, Bn, 0);
    if (nSingle > 0)
        gen_main<1><<<nSingle, 256, SMEM_TOTAL>>>(x, bi, Wf, bf, b1, b2, (float*)d_out, Bn, nPair * 256);
}